// round 4
// baseline (speedup 1.0000x reference)
#include <cuda_runtime.h>
#include <cuda_bf16.h>
#include <math.h>

// Problem dims (fixed by the reference setup)
#define BB 8
#define CC 512
#define LL 2048
#define NG 32
#define CPG 16   // channels per group

static const long long CL  = (long long)CC * LL;      // 1,048,576
static const long long LL2 = (long long)LL * LL;      // 4,194,304

// ---------------- scratch (device globals; no cudaMalloc allowed) ----------
__device__ float g_h [BB * CC * LL];   // groupnorm output
__device__ float g_q [BB * CC * LL];
__device__ float g_k [BB * CC * LL];
__device__ float g_v [BB * CC * LL];
__device__ float g_s [(long long)BB * LL * LL];  // attention scores (128 MB)
__device__ float g_h2[BB * CC * LL];   // attn output (pre out-proj)

// ---------------- GroupNorm ------------------------------------------------
// one block per (batch, group): reduce over 16*2048 = 32768 elements
__global__ void __launch_bounds__(256)
gn_kernel(const float* __restrict__ x, const float* __restrict__ gw,
          const float* __restrict__ gb, float* __restrict__ h)
{
    const int blk   = blockIdx.x;       // 0..255
    const int batch = blk >> 5;
    const int g     = blk & 31;
    const long long base = (long long)batch * CC * LL + (long long)g * CPG * LL;
    const float* xp = x + base;
    float*       hp = h + base;
    const int tid = threadIdx.x;
    const int NEL = CPG * LL;           // 32768

    float s = 0.f, ss = 0.f;
    for (int i = tid; i < NEL; i += 256) {
        float v = xp[i];
        s += v; ss += v * v;
    }
    __shared__ float rs[32], rss[32];
    #pragma unroll
    for (int o = 16; o; o >>= 1) {
        s  += __shfl_xor_sync(0xffffffffu, s,  o);
        ss += __shfl_xor_sync(0xffffffffu, ss, o);
    }
    const int warp = tid >> 5, lane = tid & 31;
    if (!lane) { rs[warp] = s; rss[warp] = ss; }
    __syncthreads();
    if (tid < 32) {
        float s2  = (tid < 8) ? rs[tid]  : 0.f;
        float ss2 = (tid < 8) ? rss[tid] : 0.f;
        #pragma unroll
        for (int o = 4; o; o >>= 1) {
            s2  += __shfl_xor_sync(0xffffffffu, s2,  o);
            ss2 += __shfl_xor_sync(0xffffffffu, ss2, o);
        }
        if (!tid) {
            float mean = s2 / (float)NEL;
            float var  = ss2 / (float)NEL - mean * mean;
            rs[0]  = mean;
            rss[0] = rsqrtf(var + 1e-6f);
        }
    }
    __syncthreads();
    const float mean = rs[0], inv = rss[0];
    for (int i = tid; i < NEL; i += 256) {
        int c = g * CPG + (i >> 11);    // i / 2048
        hp[i] = (xp[i] - mean) * inv * gw[c] + gb[c];
    }
}

// ---------------- tiled SGEMM ----------------------------------------------
// C[m,n] = alpha * sum_k opA(A)[m,k] * opB(B)[k,n]  (+ bias[m]) (+ res[m,n])
//   TA=false: A[m*lda + k]   TA=true: A[k*lda + m]
//   TB=false: B[k*ldb + n]   TB=true: B[n*ldb + k]
// Block tile 128x128, K-tile 16, 256 threads, 8x8 per thread.
// All dims are multiples of the tile sizes here -> no bounds checks.
template<bool TA, bool TB>
__global__ void __launch_bounds__(256)
gemm_kernel(const float* __restrict__ A, long long sA,
            const float* __restrict__ B, long long sB,
            const float* __restrict__ bias,
            const float* __restrict__ res, long long sRes,
            float* __restrict__ C, long long sC,
            int K, int lda, int ldb, int ldc, float alpha)
{
    __shared__ float As[16][132];   // rows 528B = 33*16B -> 16B aligned
    __shared__ float Bs[16][132];

    const int z = blockIdx.z;
    A += (long long)z * sA;
    B += (long long)z * sB;
    C += (long long)z * sC;
    const float* R = res ? res + (long long)z * sRes : nullptr;

    const int bm  = blockIdx.y * 128;
    const int bn  = blockIdx.x * 128;
    const int tid = threadIdx.x;
    const int ty  = tid >> 4, tx = tid & 15;

    float acc[8][8];
    #pragma unroll
    for (int i = 0; i < 8; i++)
        #pragma unroll
        for (int j = 0; j < 8; j++) acc[i][j] = 0.f;

    for (int k0 = 0; k0 < K; k0 += 16) {
        #pragma unroll
        for (int i = 0; i < 8; i++) {
            int idx = tid + i * 256;
            if (TA) {
                int k = idx >> 7, m = idx & 127;
                As[k][m] = A[(long long)(k0 + k) * lda + bm + m];
            } else {
                int m = idx >> 4, k = idx & 15;
                As[k][m] = A[(long long)(bm + m) * lda + k0 + k];
            }
        }
        #pragma unroll
        for (int i = 0; i < 8; i++) {
            int idx = tid + i * 256;
            if (TB) {
                int n = idx >> 4, k = idx & 15;
                Bs[k][n] = B[(long long)(bn + n) * ldb + k0 + k];
            } else {
                int k = idx >> 7, n = idx & 127;
                Bs[k][n] = B[(long long)(k0 + k) * ldb + bn + n];
            }
        }
        __syncthreads();

        #pragma unroll
        for (int k = 0; k < 16; k++) {
            float a[8], b[8];
            #pragma unroll
            for (int i = 0; i < 8; i++) a[i] = As[k][ty * 8 + i];
            #pragma unroll
            for (int j = 0; j < 8; j++) b[j] = Bs[k][tx * 8 + j];
            #pragma unroll
            for (int i = 0; i < 8; i++)
                #pragma unroll
                for (int j = 0; j < 8; j++)
                    acc[i][j] = fmaf(a[i], b[j], acc[i][j]);
        }
        __syncthreads();
    }

    #pragma unroll
    for (int i = 0; i < 8; i++) {
        const int m = bm + ty * 8 + i;
        const float bi = bias ? bias[m] : 0.f;
        #pragma unroll
        for (int j = 0; j < 8; j++) {
            const int n = bn + tx * 8 + j;
            float v = acc[i][j] * alpha + bi;
            if (R) v += R[(long long)m * ldc + n];
            C[(long long)m * ldc + n] = v;
        }
    }
}

// ---------------- row softmax (L=2048, one block/row) ------------------------
__global__ void __launch_bounds__(256)
softmax_kernel(float* __restrict__ sm)
{
    float* row = sm + (long long)blockIdx.x * LL;
    const int tid = threadIdx.x;
    const int warp = tid >> 5, lane = tid & 31;

    float v[8];
    float mx = -1e30f;
    #pragma unroll
    for (int i = 0; i < 8; i++) {
        v[i] = row[tid + 256 * i];
        mx = fmaxf(mx, v[i]);
    }
    __shared__ float red[32];
    __shared__ float bcast;
    #pragma unroll
    for (int o = 16; o; o >>= 1) mx = fmaxf(mx, __shfl_xor_sync(0xffffffffu, mx, o));
    if (!lane) red[warp] = mx;
    __syncthreads();
    if (tid < 32) {
        float m2 = (tid < 8) ? red[tid] : -1e30f;
        #pragma unroll
        for (int o = 4; o; o >>= 1) m2 = fmaxf(m2, __shfl_xor_sync(0xffffffffu, m2, o));
        if (!tid) bcast = m2;
    }
    __syncthreads();
    mx = bcast;

    float s = 0.f;
    #pragma unroll
    for (int i = 0; i < 8; i++) {
        v[i] = expf(v[i] - mx);
        s += v[i];
    }
    #pragma unroll
    for (int o = 16; o; o >>= 1) s += __shfl_xor_sync(0xffffffffu, s, o);
    if (!lane) red[warp] = s;
    __syncthreads();
    if (tid < 32) {
        float s2 = (tid < 8) ? red[tid] : 0.f;
        #pragma unroll
        for (int o = 4; o; o >>= 1) s2 += __shfl_xor_sync(0xffffffffu, s2, o);
        if (!tid) bcast = s2;
    }
    __syncthreads();
    const float inv = 1.f / bcast;
    #pragma unroll
    for (int i = 0; i < 8; i++) row[tid + 256 * i] = v[i] * inv;
}

// ---------------- launch ------------------------------------------------------
extern "C" void kernel_launch(void* const* d_in, const int* in_sizes, int n_in,
                              void* d_out, int out_size)
{
    const float* x  = (const float*)d_in[0];
    const float* gw = (const float*)d_in[1];
    const float* gb = (const float*)d_in[2];
    const float* wq = (const float*)d_in[3];
    const float* bq = (const float*)d_in[4];
    const float* wk = (const float*)d_in[5];
    const float* bk = (const float*)d_in[6];
    const float* wv = (const float*)d_in[7];
    const float* bv = (const float*)d_in[8];
    const float* wo = (const float*)d_in[9];
    const float* bo = (const float*)d_in[10];
    float* out = (float*)d_out;

    float *h, *q, *k, *v, *s, *h2;
    cudaGetSymbolAddress((void**)&h,  g_h);
    cudaGetSymbolAddress((void**)&q,  g_q);
    cudaGetSymbolAddress((void**)&k,  g_k);
    cudaGetSymbolAddress((void**)&v,  g_v);
    cudaGetSymbolAddress((void**)&s,  g_s);
    cudaGetSymbolAddress((void**)&h2, g_h2);

    const float scale = 0.044194173824159216f;   // 512^-0.5

    // 1) GroupNorm
    gn_kernel<<<BB * NG, 256>>>(x, gw, gb, h);

    // 2) Q/K/V = W(512x512) @ H_b(512x2048) + bias   (NN)
    dim3 blk(256);
    dim3 gQKV(LL / 128, CC / 128, BB);   // (16,4,8)
    gemm_kernel<false, false><<<gQKV, blk>>>(wq, 0LL, h, CL, bq, nullptr, 0LL,
                                             q, CL, CC, CC, LL, LL, 1.f);
    gemm_kernel<false, false><<<gQKV, blk>>>(wk, 0LL, h, CL, bk, nullptr, 0LL,
                                             k, CL, CC, CC, LL, LL, 1.f);
    gemm_kernel<false, false><<<gQKV, blk>>>(wv, 0LL, h, CL, bv, nullptr, 0LL,
                                             v, CL, CC, CC, LL, LL, 1.f);

    // 3) S_b = scale * Q_b^T @ K_b   (TN: A[k*lda+m] with lda=L)
    dim3 gS(LL / 128, LL / 128, BB);     // (16,16,8)
    gemm_kernel<true, false><<<gS, blk>>>(q, CL, k, CL, nullptr, nullptr, 0LL,
                                          s, LL2, CC, LL, LL, LL, scale);

    // 4) row softmax over j
    softmax_kernel<<<BB * LL, 256>>>(s);

    // 5) H2_b = V_b @ S_b^T   (NT: B[n*ldb+k] with ldb=L)
    dim3 gAV(LL / 128, CC / 128, BB);
    gemm_kernel<false, true><<<gAV, blk>>>(v, CL, s, LL2, nullptr, nullptr, 0LL,
                                           h2, CL, LL, LL, LL, LL, 1.f);

    // 6) out = x + Wo @ H2_b + bo
    gemm_kernel<false, false><<<gAV, blk>>>(wo, 0LL, h2, CL, bo, x, CL,
                                            out, CL, CC, CC, LL, LL, 1.f);
}

// round 5
// speedup vs baseline: 3.2498x; 3.2498x over previous
#include <cuda_runtime.h>
#include <math.h>
#include <stdint.h>

// Problem dims (fixed by the reference setup)
#define BB 8
#define CC 512
#define LL 2048
#define NG 32
#define CPG 16

static const long long CL  = (long long)CC * LL;      // 1,048,576
static const long long LL2 = (long long)LL * LL;      // 4,194,304

// ---------------- scratch (device globals; no cudaMalloc allowed) ----------
__device__ float g_h [BB * CC * LL];             // groupnorm out, then reused as q^T
__device__ float g_q [BB * CC * LL];
__device__ float g_k [BB * CC * LL];
__device__ float g_v [BB * CC * LL];
__device__ float g_h2[BB * CC * LL];
__device__ float g_s [(long long)BB * LL * LL];  // scores / softmax (128 MB)
__device__ float g_s2[(long long)BB * LL * LL];  // softmax transposed (128 MB)

// ---------------- GroupNorm ------------------------------------------------
__global__ void __launch_bounds__(256)
gn_kernel(const float* __restrict__ x, const float* __restrict__ gw,
          const float* __restrict__ gb, float* __restrict__ h)
{
    const int blk   = blockIdx.x;
    const int batch = blk >> 5;
    const int g     = blk & 31;
    const long long base = (long long)batch * CC * LL + (long long)g * CPG * LL;
    const float* xp = x + base;
    float*       hp = h + base;
    const int tid = threadIdx.x;
    const int NEL = CPG * LL;   // 32768

    float s = 0.f, ss = 0.f;
    for (int i = tid; i < NEL; i += 256) {
        float v = xp[i];
        s += v; ss += v * v;
    }
    __shared__ float rs[32], rss[32];
    #pragma unroll
    for (int o = 16; o; o >>= 1) {
        s  += __shfl_xor_sync(0xffffffffu, s,  o);
        ss += __shfl_xor_sync(0xffffffffu, ss, o);
    }
    const int warp = tid >> 5, lane = tid & 31;
    if (!lane) { rs[warp] = s; rss[warp] = ss; }
    __syncthreads();
    if (tid < 32) {
        float s2  = (tid < 8) ? rs[tid]  : 0.f;
        float ss2 = (tid < 8) ? rss[tid] : 0.f;
        #pragma unroll
        for (int o = 4; o; o >>= 1) {
            s2  += __shfl_xor_sync(0xffffffffu, s2,  o);
            ss2 += __shfl_xor_sync(0xffffffffu, ss2, o);
        }
        if (!tid) {
            float mean = s2 / (float)NEL;
            float var  = ss2 / (float)NEL - mean * mean;
            rs[0]  = mean;
            rss[0] = rsqrtf(var + 1e-6f);
        }
    }
    __syncthreads();
    const float mean = rs[0], inv = rss[0];
    for (int i = tid; i < NEL; i += 256) {
        int c = g * CPG + (i >> 11);
        hp[i] = (xp[i] - mean) * inv * gw[c] + gb[c];
    }
}

// ---------------- batched 32x32 tiled transpose ------------------------------
// out[c][r] = in[r][c]; in is R x Cd (row-major), out is Cd x R.
__global__ void __launch_bounds__(256)
transpose_kernel(const float* __restrict__ in, float* __restrict__ out,
                 int R, int Cd)
{
    __shared__ float tile[32][33];
    const long long zo = (long long)blockIdx.z * (long long)R * Cd;
    const int c0 = blockIdx.x * 32, r0 = blockIdx.y * 32;
    const int x = threadIdx.x & 31, y = threadIdx.x >> 5;  // 32 x 8

    #pragma unroll
    for (int i = 0; i < 4; i++)
        tile[y + 8 * i][x] = in[zo + (long long)(r0 + y + 8 * i) * Cd + c0 + x];
    __syncthreads();
    #pragma unroll
    for (int i = 0; i < 4; i++)
        out[zo + (long long)(c0 + y + 8 * i) * R + r0 + x] = tile[x][y + 8 * i];
}

// ---------------- tf32 tensor-core GEMM (NN only) ----------------------------
// C[m,n] = alpha * sum_k A[m*lda+k] * B[k*ldb+n] (+ bias[m]) (+ res[m*ldc+n])
// Block 128x128x32, 8 warps of 64x32, mma.sync m16n8k8 tf32, cp.async dbuf.
#define BM 128
#define BN 128
#define BK 32
#define ASTR 36     // As row stride (floats): frag banks = 4g+t (conflict-free)
#define BSTR 136    // Bs row stride (floats): frag banks = 8t+g (conflict-free)
#define ASZ (BM * ASTR)
#define BSZ (BK * BSTR)
#define GEMM_SMEM ((2 * ASZ + 2 * BSZ) * 4)   // 71680 B

__device__ __forceinline__ uint32_t f2tf(float f) {
    uint32_t u;
    asm("cvt.rna.tf32.f32 %0, %1;" : "=r"(u) : "f"(f));
    return u;
}

__device__ __forceinline__ void cp16(uint32_t dst, const float* src) {
    asm volatile("cp.async.ca.shared.global [%0], [%1], 16;" :: "r"(dst), "l"(src));
}

__device__ __forceinline__ void mma8(float* c, const uint32_t* a, const uint32_t* b) {
    asm volatile(
        "mma.sync.aligned.m16n8k8.row.col.f32.tf32.tf32.f32 "
        "{%0,%1,%2,%3}, {%4,%5,%6,%7}, {%8,%9}, {%0,%1,%2,%3};"
        : "+f"(c[0]), "+f"(c[1]), "+f"(c[2]), "+f"(c[3])
        : "r"(a[0]), "r"(a[1]), "r"(a[2]), "r"(a[3]), "r"(b[0]), "r"(b[1]));
}

__global__ void __launch_bounds__(256, 2)
gemm_tf32_nn(const float* __restrict__ A, long long sA,
             const float* __restrict__ B, long long sB,
             const float* __restrict__ bias,
             const float* __restrict__ res, long long sRes,
             float* __restrict__ C, long long sC,
             int K, int lda, int ldb, int ldc, float alpha)
{
    extern __shared__ float smf[];
    float* As = smf;                 // 2 buffers of [128][36]
    float* Bs = smf + 2 * ASZ;       // 2 buffers of [32][136]

    const int z = blockIdx.z;
    A += (long long)z * sA;
    B += (long long)z * sB;
    C += (long long)z * sC;
    const float* R = res ? res + (long long)z * sRes : nullptr;

    const int bm = blockIdx.y * BM;
    const int bn = blockIdx.x * BN;
    const int tid  = threadIdx.x;
    const int warp = tid >> 5, lane = tid & 31;
    const int wm = warp >> 2, wn = warp & 3;   // 2x4 warp grid
    const int g  = lane >> 2, t  = lane & 3;

    // fill index mapping (float4 loads, coalesced)
    const int a_kq = tid & 7,  a_m = tid >> 3;   // A: 8 k-quads x 32 m rows
    const int b_nq = tid & 31, b_k = tid >> 5;   // B: 32 n-quads x 8 k rows

    const uint32_t as_u = (uint32_t)__cvta_generic_to_shared(As);
    const uint32_t bs_u = (uint32_t)__cvta_generic_to_shared(Bs);

    float acc[4][4][4];
    #pragma unroll
    for (int i = 0; i < 4; i++)
        #pragma unroll
        for (int j = 0; j < 4; j++)
            #pragma unroll
            for (int q = 0; q < 4; q++) acc[i][j][q] = 0.f;

    auto fill = [&](int buf, int k0) {
        const uint32_t ab = as_u + (uint32_t)(buf * ASZ * 4);
        const uint32_t bb = bs_u + (uint32_t)(buf * BSZ * 4);
        #pragma unroll
        for (int mi = 0; mi < 4; mi++) {
            const int row = a_m + 32 * mi;
            cp16(ab + (uint32_t)((row * ASTR + a_kq * 4) * 4),
                 A + (long long)(bm + row) * lda + k0 + a_kq * 4);
        }
        #pragma unroll
        for (int ki = 0; ki < 4; ki++) {
            const int k = b_k + 8 * ki;
            cp16(bb + (uint32_t)((k * BSTR + b_nq * 4) * 4),
                 B + (long long)(k0 + k) * ldb + bn + b_nq * 4);
        }
        asm volatile("cp.async.commit_group;" ::: "memory");
    };

    const int nk = K / BK;
    fill(0, 0);
    int buf = 0;

    for (int ks = 0; ks < nk; ks++) {
        if (ks + 1 < nk) {
            fill(buf ^ 1, (ks + 1) * BK);
            asm volatile("cp.async.wait_group 1;" ::: "memory");
        } else {
            asm volatile("cp.async.wait_group 0;" ::: "memory");
        }
        __syncthreads();

        const float* Ab = As + buf * ASZ;
        const float* Bb = Bs + buf * BSZ;

        #pragma unroll
        for (int k8 = 0; k8 < 4; k8++) {
            const int kk = k8 * 8;
            uint32_t bf[4][2];
            #pragma unroll
            for (int nt = 0; nt < 4; nt++) {
                const int col = wn * 32 + nt * 8 + g;
                bf[nt][0] = f2tf(Bb[(kk + t) * BSTR + col]);
                bf[nt][1] = f2tf(Bb[(kk + t + 4) * BSTR + col]);
            }
            #pragma unroll
            for (int mt = 0; mt < 4; mt++) {
                const int row = wm * 64 + mt * 16 + g;
                uint32_t af[4];
                af[0] = f2tf(Ab[row * ASTR + kk + t]);
                af[1] = f2tf(Ab[(row + 8) * ASTR + kk + t]);
                af[2] = f2tf(Ab[row * ASTR + kk + t + 4]);
                af[3] = f2tf(Ab[(row + 8) * ASTR + kk + t + 4]);
                #pragma unroll
                for (int nt = 0; nt < 4; nt++)
                    mma8(acc[mt][nt], af, bf[nt]);
            }
        }
        __syncthreads();
        buf ^= 1;
    }

    // epilogue: c0:(g,2t) c1:(g,2t+1) c2:(g+8,2t) c3:(g+8,2t+1)
    #pragma unroll
    for (int mt = 0; mt < 4; mt++) {
        const int r0 = bm + wm * 64 + mt * 16 + g;
        const float bi0 = bias ? bias[r0]     : 0.f;
        const float bi1 = bias ? bias[r0 + 8] : 0.f;
        #pragma unroll
        for (int nt = 0; nt < 4; nt++) {
            const int c0 = bn + wn * 32 + nt * 8 + 2 * t;
            float2 v0, v1;
            v0.x = acc[mt][nt][0] * alpha + bi0;
            v0.y = acc[mt][nt][1] * alpha + bi0;
            v1.x = acc[mt][nt][2] * alpha + bi1;
            v1.y = acc[mt][nt][3] * alpha + bi1;
            if (R) {
                const float2 r0v = *(const float2*)&R[(long long)r0 * ldc + c0];
                const float2 r1v = *(const float2*)&R[(long long)(r0 + 8) * ldc + c0];
                v0.x += r0v.x; v0.y += r0v.y;
                v1.x += r1v.x; v1.y += r1v.y;
            }
            *(float2*)&C[(long long)r0 * ldc + c0]       = v0;
            *(float2*)&C[(long long)(r0 + 8) * ldc + c0] = v1;
        }
    }
}

// ---------------- row softmax (L=2048, one block/row) ------------------------
__global__ void __launch_bounds__(256)
softmax_kernel(float* __restrict__ sm)
{
    float* row = sm + (long long)blockIdx.x * LL;
    const int tid = threadIdx.x;
    const int warp = tid >> 5, lane = tid & 31;

    float v[8];
    float mx = -1e30f;
    #pragma unroll
    for (int i = 0; i < 8; i++) {
        v[i] = row[tid + 256 * i];
        mx = fmaxf(mx, v[i]);
    }
    __shared__ float red[32];
    __shared__ float bcast;
    #pragma unroll
    for (int o = 16; o; o >>= 1) mx = fmaxf(mx, __shfl_xor_sync(0xffffffffu, mx, o));
    if (!lane) red[warp] = mx;
    __syncthreads();
    if (tid < 32) {
        float m2 = (tid < 8) ? red[tid] : -1e30f;
        #pragma unroll
        for (int o = 4; o; o >>= 1) m2 = fmaxf(m2, __shfl_xor_sync(0xffffffffu, m2, o));
        if (!tid) bcast = m2;
    }
    __syncthreads();
    mx = bcast;

    float s = 0.f;
    #pragma unroll
    for (int i = 0; i < 8; i++) {
        v[i] = expf(v[i] - mx);
        s += v[i];
    }
    #pragma unroll
    for (int o = 16; o; o >>= 1) s += __shfl_xor_sync(0xffffffffu, s, o);
    if (!lane) red[warp] = s;
    __syncthreads();
    if (tid < 32) {
        float s2 = (tid < 8) ? red[tid] : 0.f;
        #pragma unroll
        for (int o = 4; o; o >>= 1) s2 += __shfl_xor_sync(0xffffffffu, s2, o);
        if (!tid) bcast = s2;
    }
    __syncthreads();
    const float inv = 1.f / bcast;
    #pragma unroll
    for (int i = 0; i < 8; i++) row[tid + 256 * i] = v[i] * inv;
}

// ---------------- launch ------------------------------------------------------
extern "C" void kernel_launch(void* const* d_in, const int* in_sizes, int n_in,
                              void* d_out, int out_size)
{
    const float* x  = (const float*)d_in[0];
    const float* gw = (const float*)d_in[1];
    const float* gb = (const float*)d_in[2];
    const float* wq = (const float*)d_in[3];
    const float* bq = (const float*)d_in[4];
    const float* wk = (const float*)d_in[5];
    const float* bk = (const float*)d_in[6];
    const float* wv = (const float*)d_in[7];
    const float* bv = (const float*)d_in[8];
    const float* wo = (const float*)d_in[9];
    const float* bo = (const float*)d_in[10];
    float* out = (float*)d_out;

    float *h, *q, *k, *v, *s, *s2, *h2;
    cudaGetSymbolAddress((void**)&h,  g_h);
    cudaGetSymbolAddress((void**)&q,  g_q);
    cudaGetSymbolAddress((void**)&k,  g_k);
    cudaGetSymbolAddress((void**)&v,  g_v);
    cudaGetSymbolAddress((void**)&s,  g_s);
    cudaGetSymbolAddress((void**)&s2, g_s2);
    cudaGetSymbolAddress((void**)&h2, g_h2);

    cudaFuncSetAttribute(gemm_tf32_nn,
                         cudaFuncAttributeMaxDynamicSharedMemorySize, GEMM_SMEM);

    const float scale = 0.044194173824159216f;   // 512^-0.5
    dim3 blk(256);

    // 1) GroupNorm
    gn_kernel<<<BB * NG, 256>>>(x, gw, gb, h);

    // 2) Q/K/V = W(512x512) @ H_b(512x2048) + bias   (NN)
    dim3 gQKV(LL / 128, CC / 128, BB);   // (16,4,8)
    gemm_tf32_nn<<<gQKV, blk, GEMM_SMEM>>>(wq, 0LL, h, CL, bq, nullptr, 0LL,
                                           q, CL, CC, CC, LL, LL, 1.f);
    gemm_tf32_nn<<<gQKV, blk, GEMM_SMEM>>>(wk, 0LL, h, CL, bk, nullptr, 0LL,
                                           k, CL, CC, CC, LL, LL, 1.f);
    gemm_tf32_nn<<<gQKV, blk, GEMM_SMEM>>>(wv, 0LL, h, CL, bv, nullptr, 0LL,
                                           v, CL, CC, CC, LL, LL, 1.f);

    // 3) qT (L x C) into g_h (h is dead after QKV)
    transpose_kernel<<<dim3(LL / 32, CC / 32, BB), 256>>>(q, h, CC, LL);

    // 4) S_b = scale * qT @ K   (NN: M=L, N=L, K=C)
    dim3 gS(LL / 128, LL / 128, BB);     // (16,16,8)
    gemm_tf32_nn<<<gS, blk, GEMM_SMEM>>>(h, CL, k, CL, nullptr, nullptr, 0LL,
                                         s, LL2, CC, CC, LL, LL, scale);

    // 5) row softmax
    softmax_kernel<<<BB * LL, 256>>>(s);

    // 6) P^T (j,i)
    transpose_kernel<<<dim3(LL / 32, LL / 32, BB), 256>>>(s, s2, LL, LL);

    // 7) H2_b = V_b @ P^T   (NN: M=C, N=L, K=L)
    dim3 gAV(LL / 128, CC / 128, BB);
    gemm_tf32_nn<<<gAV, blk, GEMM_SMEM>>>(v, CL, s2, LL2, nullptr, nullptr, 0LL,
                                          h2, CL, LL, LL, LL, LL, 1.f);

    // 8) out = x + Wo @ H2_b + bo
    gemm_tf32_nn<<<gAV, blk, GEMM_SMEM>>>(wo, 0LL, h2, CL, bo, x, CL,
                                          out, CL, CC, CC, LL, LL, 1.f);
}

// round 7
// speedup vs baseline: 3.4905x; 1.0741x over previous
#include <cuda_runtime.h>
#include <math.h>
#include <stdint.h>

// Problem dims (fixed by the reference setup)
#define BB 8
#define CC 512
#define LL 2048
#define NG 32
#define CPG 16

static const long long CL  = (long long)CC * LL;      // 1,048,576
static const long long LL2 = (long long)LL * LL;      // 4,194,304

// ---------------- scratch (device globals; no cudaMalloc allowed) ----------
__device__ float g_h [BB * CC * LL];             // gn out (tf32) -> later qT
__device__ float g_q [BB * CC * LL];             // q (tf32) -> later vT
__device__ float g_k [BB * CC * LL];             // k (tf32) -> later h2 (fp32)
__device__ float g_v [BB * CC * LL];             // v (tf32)
__device__ float g_h2[BB * CC * LL];             // H2^T (fp32)
__device__ float g_s [(long long)BB * LL * LL];  // scores -> softmax P (fp32)
__device__ float g_w [4 * CC * CC];              // tf32 copies of wq,wk,wv,wo

__device__ __forceinline__ float f2tf32(float f) {
    uint32_t u;
    asm("cvt.rna.tf32.f32 %0, %1;" : "=r"(u) : "f"(f));
    return __uint_as_float(u);
}

// ---------------- weight tf32 conversion (tiny, once per launch) -------------
__global__ void __launch_bounds__(256)
cvt_kernel(const float4* __restrict__ in, float4* __restrict__ out, int n4)
{
    int i = blockIdx.x * 256 + threadIdx.x;
    if (i < n4) {
        float4 v = in[i];
        v.x = f2tf32(v.x); v.y = f2tf32(v.y);
        v.z = f2tf32(v.z); v.w = f2tf32(v.w);
        out[i] = v;
    }
}

// ---------------- GroupNorm (writes tf32-rounded output) ---------------------
__global__ void __launch_bounds__(256)
gn_kernel(const float* __restrict__ x, const float* __restrict__ gw,
          const float* __restrict__ gb, float* __restrict__ h)
{
    const int blk   = blockIdx.x;
    const int batch = blk >> 5;
    const int g     = blk & 31;
    const long long base = (long long)batch * CC * LL + (long long)g * CPG * LL;
    const float* xp = x + base;
    float*       hp = h + base;
    const int tid = threadIdx.x;
    const int NEL = CPG * LL;   // 32768

    float s = 0.f, ss = 0.f;
    for (int i = tid; i < NEL; i += 256) {
        float v = xp[i];
        s += v; ss += v * v;
    }
    __shared__ float rs[32], rss[32];
    #pragma unroll
    for (int o = 16; o; o >>= 1) {
        s  += __shfl_xor_sync(0xffffffffu, s,  o);
        ss += __shfl_xor_sync(0xffffffffu, ss, o);
    }
    const int warp = tid >> 5, lane = tid & 31;
    if (!lane) { rs[warp] = s; rss[warp] = ss; }
    __syncthreads();
    if (tid < 32) {
        float s2  = (tid < 8) ? rs[tid]  : 0.f;
        float ss2 = (tid < 8) ? rss[tid] : 0.f;
        #pragma unroll
        for (int o = 4; o; o >>= 1) {
            s2  += __shfl_xor_sync(0xffffffffu, s2,  o);
            ss2 += __shfl_xor_sync(0xffffffffu, ss2, o);
        }
        if (!tid) {
            float mean = s2 / (float)NEL;
            float var  = ss2 / (float)NEL - mean * mean;
            rs[0]  = mean;
            rss[0] = rsqrtf(var + 1e-6f);
        }
    }
    __syncthreads();
    const float mean = rs[0], inv = rss[0];
    for (int i = tid; i < NEL; i += 256) {
        int c = g * CPG + (i >> 11);
        hp[i] = f2tf32((xp[i] - mean) * inv * gw[c] + gb[c]);
    }
}

// ---------------- batched 32x32 tiled transpose ------------------------------
// out[c][r] = in[r][c]; in is R x Cd (row-major), out is Cd x R.
__global__ void __launch_bounds__(256)
transpose_kernel(const float* __restrict__ in, float* __restrict__ out,
                 int R, int Cd)
{
    __shared__ float tile[32][33];
    const long long zo = (long long)blockIdx.z * (long long)R * Cd;
    const int c0 = blockIdx.x * 32, r0 = blockIdx.y * 32;
    const int x = threadIdx.x & 31, y = threadIdx.x >> 5;  // 32 x 8

    #pragma unroll
    for (int i = 0; i < 4; i++)
        tile[y + 8 * i][x] = in[zo + (long long)(r0 + y + 8 * i) * Cd + c0 + x];
    __syncthreads();
    #pragma unroll
    for (int i = 0; i < 4; i++)
        out[zo + (long long)(c0 + y + 8 * i) * R + r0 + x] = tile[x][y + 8 * i];
}

// ---------------- tf32 tensor-core GEMM (NN only) ----------------------------
// C[m,n] = alpha * sum_k A[m*lda+k] * B[k*ldb+n] (+ bias[m]) (+ res[m*ldc+n])
// CVTA/CVTB: apply cvt.rna.tf32 at fragment load (for fp32 operands).
// When false, the operand must already be tf32-rounded in memory.
// ROUND: tf32-round the stored output.
#define BM 128
#define BN 128
#define BK 32
#define ASTR 36     // As row stride (floats): frag banks = 4g+t (conflict-free)
#define BSTR 136    // Bs row stride (floats): frag banks = 8t+g (conflict-free)
#define ASZ (BM * ASTR)
#define BSZ (BK * BSTR)
#define GEMM_SMEM ((2 * ASZ + 2 * BSZ) * 4)   // 71680 B

__device__ __forceinline__ void cp16(uint32_t dst, const float* src) {
    asm volatile("cp.async.ca.shared.global [%0], [%1], 16;" :: "r"(dst), "l"(src));
}

template<bool DO>
__device__ __forceinline__ uint32_t maybe_cvt(uint32_t x) {
    if (DO) {
        asm("cvt.rna.tf32.f32 %0, %1;" : "=r"(x) : "f"(__uint_as_float(x)));
    }
    return x;
}

__device__ __forceinline__ void mma8(float* c, const uint32_t* a, const uint32_t* b) {
    asm volatile(
        "mma.sync.aligned.m16n8k8.row.col.f32.tf32.tf32.f32 "
        "{%0,%1,%2,%3}, {%4,%5,%6,%7}, {%8,%9}, {%0,%1,%2,%3};"
        : "+f"(c[0]), "+f"(c[1]), "+f"(c[2]), "+f"(c[3])
        : "r"(a[0]), "r"(a[1]), "r"(a[2]), "r"(a[3]), "r"(b[0]), "r"(b[1]));
}

template<bool CVTA, bool CVTB, bool ROUND>
__global__ void __launch_bounds__(256, 2)
gemm_tf32_nn(const float* __restrict__ A, long long sA,
             const float* __restrict__ B, long long sB,
             const float* __restrict__ bias,
             const float* __restrict__ res, long long sRes,
             float* __restrict__ C, long long sC,
             int K, int lda, int ldb, int ldc, float alpha)
{
    extern __shared__ float smf[];
    float* As = smf;                 // 2 buffers of [128][36]
    float* Bs = smf + 2 * ASZ;       // 2 buffers of [32][136]

    const int z = blockIdx.z;
    A += (long long)z * sA;
    B += (long long)z * sB;
    C += (long long)z * sC;
    const float* R = res ? res + (long long)z * sRes : nullptr;

    const int bm = blockIdx.y * BM;
    const int bn = blockIdx.x * BN;
    const int tid  = threadIdx.x;
    const int warp = tid >> 5, lane = tid & 31;
    const int wm = warp >> 2, wn = warp & 3;   // 2x4 warp grid
    const int g  = lane >> 2, t  = lane & 3;

    const int a_kq = tid & 7,  a_m = tid >> 3;   // A fill: 8 k-quads x 32 m rows
    const int b_nq = tid & 31, b_k = tid >> 5;   // B fill: 32 n-quads x 8 k rows

    const uint32_t as_u = (uint32_t)__cvta_generic_to_shared(As);
    const uint32_t bs_u = (uint32_t)__cvta_generic_to_shared(Bs);

    float acc[4][4][4];
    #pragma unroll
    for (int i = 0; i < 4; i++)
        #pragma unroll
        for (int j = 0; j < 4; j++)
            #pragma unroll
            for (int q = 0; q < 4; q++) acc[i][j][q] = 0.f;

    auto fill = [&](int buf, int k0) {
        const uint32_t ab = as_u + (uint32_t)(buf * ASZ * 4);
        const uint32_t bb = bs_u + (uint32_t)(buf * BSZ * 4);
        #pragma unroll
        for (int mi = 0; mi < 4; mi++) {
            const int row = a_m + 32 * mi;
            cp16(ab + (uint32_t)((row * ASTR + a_kq * 4) * 4),
                 A + (long long)(bm + row) * lda + k0 + a_kq * 4);
        }
        #pragma unroll
        for (int ki = 0; ki < 4; ki++) {
            const int k = b_k + 8 * ki;
            cp16(bb + (uint32_t)((k * BSTR + b_nq * 4) * 4),
                 B + (long long)(k0 + k) * ldb + bn + b_nq * 4);
        }
        asm volatile("cp.async.commit_group;" ::: "memory");
    };

    const int nk = K / BK;
    fill(0, 0);
    int buf = 0;

    for (int ks = 0; ks < nk; ks++) {
        if (ks + 1 < nk) {
            fill(buf ^ 1, (ks + 1) * BK);
            asm volatile("cp.async.wait_group 1;" ::: "memory");
        } else {
            asm volatile("cp.async.wait_group 0;" ::: "memory");
        }
        __syncthreads();

        const uint32_t* Ab = (const uint32_t*)(As + buf * ASZ);
        const uint32_t* Bb = (const uint32_t*)(Bs + buf * BSZ);

        #pragma unroll
        for (int k8 = 0; k8 < 4; k8++) {
            const int kk = k8 * 8;
            uint32_t bf[4][2];
            #pragma unroll
            for (int nt = 0; nt < 4; nt++) {
                const int col = wn * 32 + nt * 8 + g;
                bf[nt][0] = maybe_cvt<CVTB>(Bb[(kk + t) * BSTR + col]);
                bf[nt][1] = maybe_cvt<CVTB>(Bb[(kk + t + 4) * BSTR + col]);
            }
            #pragma unroll
            for (int mt = 0; mt < 4; mt++) {
                const int row = wm * 64 + mt * 16 + g;
                uint32_t af[4];
                af[0] = maybe_cvt<CVTA>(Ab[row * ASTR + kk + t]);
                af[1] = maybe_cvt<CVTA>(Ab[(row + 8) * ASTR + kk + t]);
                af[2] = maybe_cvt<CVTA>(Ab[row * ASTR + kk + t + 4]);
                af[3] = maybe_cvt<CVTA>(Ab[(row + 8) * ASTR + kk + t + 4]);
                #pragma unroll
                for (int nt = 0; nt < 4; nt++)
                    mma8(acc[mt][nt], af, bf[nt]);
            }
        }
        __syncthreads();
        buf ^= 1;
    }

    // epilogue: c0:(g,2t) c1:(g,2t+1) c2:(g+8,2t) c3:(g+8,2t+1)
    #pragma unroll
    for (int mt = 0; mt < 4; mt++) {
        const int r0 = bm + wm * 64 + mt * 16 + g;
        const float bi0 = bias ? bias[r0]     : 0.f;
        const float bi1 = bias ? bias[r0 + 8] : 0.f;
        #pragma unroll
        for (int nt = 0; nt < 4; nt++) {
            const int c0 = bn + wn * 32 + nt * 8 + 2 * t;
            float2 v0, v1;
            v0.x = acc[mt][nt][0] * alpha + bi0;
            v0.y = acc[mt][nt][1] * alpha + bi0;
            v1.x = acc[mt][nt][2] * alpha + bi1;
            v1.y = acc[mt][nt][3] * alpha + bi1;
            if (R) {
                const float2 r0v = *(const float2*)&R[(long long)r0 * ldc + c0];
                const float2 r1v = *(const float2*)&R[(long long)(r0 + 8) * ldc + c0];
                v0.x += r0v.x; v0.y += r0v.y;
                v1.x += r1v.x; v1.y += r1v.y;
            }
            if (ROUND) {
                v0.x = f2tf32(v0.x); v0.y = f2tf32(v0.y);
                v1.x = f2tf32(v1.x); v1.y = f2tf32(v1.y);
            }
            *(float2*)&C[(long long)r0 * ldc + c0]       = v0;
            *(float2*)&C[(long long)(r0 + 8) * ldc + c0] = v1;
        }
    }
}

// ---------------- row softmax (EXACT R5 version: expf, fp32 P) ---------------
__global__ void __launch_bounds__(256)
softmax_kernel(float* __restrict__ sm)
{
    float* row = sm + (long long)blockIdx.x * LL;
    const int tid = threadIdx.x;
    const int warp = tid >> 5, lane = tid & 31;

    float v[8];
    float mx = -1e30f;
    #pragma unroll
    for (int i = 0; i < 8; i++) {
        v[i] = row[tid + 256 * i];
        mx = fmaxf(mx, v[i]);
    }
    __shared__ float red[32];
    __shared__ float bcast;
    #pragma unroll
    for (int o = 16; o; o >>= 1) mx = fmaxf(mx, __shfl_xor_sync(0xffffffffu, mx, o));
    if (!lane) red[warp] = mx;
    __syncthreads();
    if (tid < 32) {
        float m2 = (tid < 8) ? red[tid] : -1e30f;
        #pragma unroll
        for (int o = 4; o; o >>= 1) m2 = fmaxf(m2, __shfl_xor_sync(0xffffffffu, m2, o));
        if (!tid) bcast = m2;
    }
    __syncthreads();
    mx = bcast;

    float s = 0.f;
    #pragma unroll
    for (int i = 0; i < 8; i++) {
        v[i] = expf(v[i] - mx);
        s += v[i];
    }
    #pragma unroll
    for (int o = 16; o; o >>= 1) s += __shfl_xor_sync(0xffffffffu, s, o);
    if (!lane) red[warp] = s;
    __syncthreads();
    if (tid < 32) {
        float s2 = (tid < 8) ? red[tid] : 0.f;
        #pragma unroll
        for (int o = 4; o; o >>= 1) s2 += __shfl_xor_sync(0xffffffffu, s2, o);
        if (!tid) bcast = s2;
    }
    __syncthreads();
    const float inv = 1.f / bcast;
    #pragma unroll
    for (int i = 0; i < 8; i++) row[tid + 256 * i] = v[i] * inv;
}

// ---------------- launch ------------------------------------------------------
extern "C" void kernel_launch(void* const* d_in, const int* in_sizes, int n_in,
                              void* d_out, int out_size)
{
    const float* x  = (const float*)d_in[0];
    const float* gw = (const float*)d_in[1];
    const float* gb = (const float*)d_in[2];
    const float* wq = (const float*)d_in[3];
    const float* bq = (const float*)d_in[4];
    const float* wk = (const float*)d_in[5];
    const float* bk = (const float*)d_in[6];
    const float* wv = (const float*)d_in[7];
    const float* bv = (const float*)d_in[8];
    const float* wo = (const float*)d_in[9];
    const float* bo = (const float*)d_in[10];
    float* out = (float*)d_out;

    float *h, *q, *k, *v, *s, *h2t, *w;
    cudaGetSymbolAddress((void**)&h,   g_h);
    cudaGetSymbolAddress((void**)&q,   g_q);
    cudaGetSymbolAddress((void**)&k,   g_k);
    cudaGetSymbolAddress((void**)&v,   g_v);
    cudaGetSymbolAddress((void**)&s,   g_s);
    cudaGetSymbolAddress((void**)&h2t, g_h2);
    cudaGetSymbolAddress((void**)&w,   g_w);

    float* wqt = w;
    float* wkt = w + CC * CC;
    float* wvt = w + 2 * CC * CC;
    float* wot = w + 3 * CC * CC;

    // instantiations used: <CVTA,CVTB,ROUND>
    cudaFuncSetAttribute(gemm_tf32_nn<false, false, true>,
                         cudaFuncAttributeMaxDynamicSharedMemorySize, GEMM_SMEM);
    cudaFuncSetAttribute(gemm_tf32_nn<false, false, false>,
                         cudaFuncAttributeMaxDynamicSharedMemorySize, GEMM_SMEM);
    cudaFuncSetAttribute(gemm_tf32_nn<true, false, false>,
                         cudaFuncAttributeMaxDynamicSharedMemorySize, GEMM_SMEM);
    cudaFuncSetAttribute(gemm_tf32_nn<false, true, false>,
                         cudaFuncAttributeMaxDynamicSharedMemorySize, GEMM_SMEM);

    const float scale = 0.044194173824159216f;   // 512^-0.5
    dim3 blk(256);
    const int n4 = CC * CC / 4;   // 65536
    const int cvtg = (n4 + 255) / 256;

    // 0) tf32 copies of weights
    cvt_kernel<<<cvtg, 256>>>((const float4*)wq, (float4*)wqt, n4);
    cvt_kernel<<<cvtg, 256>>>((const float4*)wk, (float4*)wkt, n4);
    cvt_kernel<<<cvtg, 256>>>((const float4*)wv, (float4*)wvt, n4);
    cvt_kernel<<<cvtg, 256>>>((const float4*)wo, (float4*)wot, n4);

    // 1) GroupNorm (tf32 out)
    gn_kernel<<<BB * NG, 256>>>(x, gw, gb, h);

    // 2) Q/K/V = W @ H_b + bias   (NN; operands pre-rounded; round outputs)
    dim3 gQKV(LL / 128, CC / 128, BB);   // (16,4,8)
    gemm_tf32_nn<false, false, true><<<gQKV, blk, GEMM_SMEM>>>(
        wqt, 0LL, h, CL, bq, nullptr, 0LL, q, CL, CC, CC, LL, LL, 1.f);
    gemm_tf32_nn<false, false, true><<<gQKV, blk, GEMM_SMEM>>>(
        wkt, 0LL, h, CL, bk, nullptr, 0LL, k, CL, CC, CC, LL, LL, 1.f);
    gemm_tf32_nn<false, false, true><<<gQKV, blk, GEMM_SMEM>>>(
        wvt, 0LL, h, CL, bv, nullptr, 0LL, v, CL, CC, CC, LL, LL, 1.f);

    // 3) qT (L x C) into g_h (h dead after QKV)
    transpose_kernel<<<dim3(LL / 32, CC / 32, BB), 256>>>(q, h, CC, LL);

    // 4) S_b = scale * qT @ K   (operands tf32 already; fp32 scores out)
    dim3 gS(LL / 128, LL / 128, BB);     // (16,16,8)
    gemm_tf32_nn<false, false, false><<<gS, blk, GEMM_SMEM>>>(
        h, CL, k, CL, nullptr, nullptr, 0LL, s, LL2, CC, CC, LL, LL, scale);

    // 5) row softmax (fp32 in/out, exact R5)
    softmax_kernel<<<BB * LL, 256>>>(s);

    // 6) vT (L x C) into g_q (q dead after qT transpose)
    transpose_kernel<<<dim3(LL / 32, CC / 32, BB), 256>>>(v, q, CC, LL);

    // 7) H2^T = P @ vT   (A=P fp32 -> cvt at load; B=vT tf32; fp32 out)
    dim3 gAV(CC / 128, LL / 128, BB);    // (4,16,8)
    gemm_tf32_nn<true, false, false><<<gAV, blk, GEMM_SMEM>>>(
        s, LL2, q, CL, nullptr, nullptr, 0LL, h2t, CL, LL, LL, CC, CC, 1.f);

    // 8) h2 (C x L) into g_k (k dead after scores gemm)
    transpose_kernel<<<dim3(CC / 32, LL / 32, BB), 256>>>(h2t, k, LL, CC);

    // 9) out = x + Wo @ h2 + bo   (A=wo tf32; B=h2 fp32 -> cvt at load)
    dim3 gO(LL / 128, CC / 128, BB);
    gemm_tf32_nn<false, true, false><<<gO, blk, GEMM_SMEM>>>(
        wot, 0LL, k, CL, bo, x, CL, out, CL, CC, CC, LL, LL, 1.f);
}

// round 10
// speedup vs baseline: 3.8500x; 1.1030x over previous
#include <cuda_runtime.h>
#include <math.h>
#include <stdint.h>

// Problem dims (fixed by the reference setup)
#define BB 8
#define CC 512
#define LL 2048
#define NG 32
#define CPG 16

static const long long CL  = (long long)CC * LL;      // 1,048,576
static const long long LL2 = (long long)LL * LL;      // 4,194,304

// ---------------- scratch (device globals; no cudaMalloc allowed) ----------
__device__ float g_h [BB * CC * LL];             // gn out h [C][L]; later vT [L][C]
__device__ float g_ht[BB * CC * LL];             // qT [L][C]
__device__ float g_q [BB * CC * LL];             // q [C][L]; later h2T [L][C]
__device__ float g_k [BB * CC * LL];             // k [C][L]; later h2 [C][L]
__device__ float g_v [BB * CC * LL];             // v [C][L]
__device__ float g_s [(long long)BB * LL * LL];  // scores -> softmax P [L][L]
__device__ float g_w [4 * CC * CC];              // tf32 copies of wq,wk,wv,wo

__device__ __forceinline__ float f2tf32(float f) {
    uint32_t u;
    asm("cvt.rna.tf32.f32 %0, %1;" : "=r"(u) : "f"(f));
    return __uint_as_float(u);
}

// ---------------- weight tf32 conversion (one launch) ------------------------
__global__ void __launch_bounds__(256)
cvt4_kernel(const float4* __restrict__ a, const float4* __restrict__ b,
            const float4* __restrict__ c, const float4* __restrict__ d,
            float4* __restrict__ out)
{
    int i = blockIdx.x * 256 + threadIdx.x;       // 0 .. 262143
    int seg = i >> 16, off = i & 65535;
    const float4* src = (seg == 0) ? a : (seg == 1) ? b : (seg == 2) ? c : d;
    float4 v = src[off];
    v.x = f2tf32(v.x); v.y = f2tf32(v.y);
    v.z = f2tf32(v.z); v.w = f2tf32(v.w);
    out[i] = v;
}

// ---------------- GroupNorm (writes tf32-rounded output) ---------------------
__global__ void __launch_bounds__(256)
gn_kernel(const float* __restrict__ x, const float* __restrict__ gw,
          const float* __restrict__ gb, float* __restrict__ h)
{
    const int blk   = blockIdx.x;
    const int batch = blk >> 5;
    const int g     = blk & 31;
    const long long base = (long long)batch * CC * LL + (long long)g * CPG * LL;
    const float* xp = x + base;
    float*       hp = h + base;
    const int tid = threadIdx.x;
    const int NEL = CPG * LL;   // 32768

    float s = 0.f, ss = 0.f;
    for (int i = tid; i < NEL; i += 256) {
        float v = xp[i];
        s += v; ss += v * v;
    }
    __shared__ float rs[32], rss[32];
    #pragma unroll
    for (int o = 16; o; o >>= 1) {
        s  += __shfl_xor_sync(0xffffffffu, s,  o);
        ss += __shfl_xor_sync(0xffffffffu, ss, o);
    }
    const int warp = tid >> 5, lane = tid & 31;
    if (!lane) { rs[warp] = s; rss[warp] = ss; }
    __syncthreads();
    if (tid < 32) {
        float s2  = (tid < 8) ? rs[tid]  : 0.f;
        float ss2 = (tid < 8) ? rss[tid] : 0.f;
        #pragma unroll
        for (int o = 4; o; o >>= 1) {
            s2  += __shfl_xor_sync(0xffffffffu, s2,  o);
            ss2 += __shfl_xor_sync(0xffffffffu, ss2, o);
        }
        if (!tid) {
            float mean = s2 / (float)NEL;
            float var  = ss2 / (float)NEL - mean * mean;
            rs[0]  = mean;
            rss[0] = rsqrtf(var + 1e-6f);
        }
    }
    __syncthreads();
    const float mean = rs[0], inv = rss[0];
    for (int i = tid; i < NEL; i += 256) {
        int c = g * CPG + (i >> 11);
        hp[i] = f2tf32((xp[i] - mean) * inv * gw[c] + gb[c]);
    }
}

// ---------------- batched 32x32 tiled transpose ------------------------------
__global__ void __launch_bounds__(256)
transpose_kernel(const float* __restrict__ in, float* __restrict__ out,
                 int R, int Cd)
{
    __shared__ float tile[32][33];
    const long long zo = (long long)blockIdx.z * (long long)R * Cd;
    const int c0 = blockIdx.x * 32, r0 = blockIdx.y * 32;
    const int x = threadIdx.x & 31, y = threadIdx.x >> 5;

    #pragma unroll
    for (int i = 0; i < 4; i++)
        tile[y + 8 * i][x] = in[zo + (long long)(r0 + y + 8 * i) * Cd + c0 + x];
    __syncthreads();
    #pragma unroll
    for (int i = 0; i < 4; i++)
        out[zo + (long long)(c0 + y + 8 * i) * R + r0 + x] = tile[x][y + 8 * i];
}

// ---------------- tf32 mma.sync GEMM, 128x256 tile, 64x64 warp tile ----------
// C[m,n] = alpha * sum_k A[m*lda+k] * B[k*ldb+n] (+ bias[m]) (+ res[m*ldc+n])
// All operands MUST be tf32-pre-rounded. ROUND: tf32-round outputs.
#define BM 128
#define BN 256
#define BK 32
#define ASTR 36     // 36 mod 32 = 4 -> A frag banks = 4g + t (conflict-free)
#define BSTR 264    // 264 mod 32 = 8 -> B frag banks = 8t + g (conflict-free)
#define ASZ (BM * ASTR)     // 4608 floats
#define BSZ (BK * BSTR)     // 8448 floats
#define GEMM_SMEM ((2 * ASZ + 2 * BSZ) * 4)   // 104448 B

__device__ __forceinline__ void cp16(uint32_t dst, const float* src) {
    asm volatile("cp.async.ca.shared.global [%0], [%1], 16;" :: "r"(dst), "l"(src));
}

__device__ __forceinline__ void mma8(float* c, const uint32_t* a, const uint32_t* b) {
    asm volatile(
        "mma.sync.aligned.m16n8k8.row.col.f32.tf32.tf32.f32 "
        "{%0,%1,%2,%3}, {%4,%5,%6,%7}, {%8,%9}, {%0,%1,%2,%3};"
        : "+f"(c[0]), "+f"(c[1]), "+f"(c[2]), "+f"(c[3])
        : "r"(a[0]), "r"(a[1]), "r"(a[2]), "r"(a[3]), "r"(b[0]), "r"(b[1]));
}

template<bool ROUND>
__global__ void __launch_bounds__(256, 1)
gemm_tf32_nn(const float* __restrict__ A, long long sA,
             const float* __restrict__ B, long long sB,
             const float* __restrict__ bias,
             const float* __restrict__ res, long long sRes,
             float* __restrict__ C, long long sC,
             int K, int lda, int ldb, int ldc, float alpha)
{
    extern __shared__ float smf[];
    float* As = smf;                 // 2 buffers of [128][36]
    float* Bs = smf + 2 * ASZ;       // 2 buffers of [32][264]

    const int z = blockIdx.z;
    A += (long long)z * sA;
    B += (long long)z * sB;
    C += (long long)z * sC;
    const float* R = res ? res + (long long)z * sRes : nullptr;

    const int bm = blockIdx.y * BM;
    const int bn = blockIdx.x * BN;
    const int tid  = threadIdx.x;
    const int warp = tid >> 5, lane = tid & 31;
    const int wm = warp >> 2, wn = warp & 3;   // 2x4 warp grid, 64x64 each
    const int g  = lane >> 2, t  = lane & 3;

    const int a_kq = tid & 7,  a_m = tid >> 3;   // A fill: 8 k-quads x 32 rows
    const int b_nq = tid & 63, b_k = tid >> 6;   // B fill: 64 n-quads x 4 k rows

    const uint32_t as_u = (uint32_t)__cvta_generic_to_shared(As);
    const uint32_t bs_u = (uint32_t)__cvta_generic_to_shared(Bs);

    float acc[4][8][4];
    #pragma unroll
    for (int i = 0; i < 4; i++)
        #pragma unroll
        for (int j = 0; j < 8; j++)
            #pragma unroll
            for (int q = 0; q < 4; q++) acc[i][j][q] = 0.f;

    auto fill = [&](int buf, int k0) {
        const uint32_t ab = as_u + (uint32_t)(buf * ASZ * 4);
        const uint32_t bb = bs_u + (uint32_t)(buf * BSZ * 4);
        #pragma unroll
        for (int mi = 0; mi < 4; mi++) {
            const int row = a_m + 32 * mi;
            cp16(ab + (uint32_t)((row * ASTR + a_kq * 4) * 4),
                 A + (long long)(bm + row) * lda + k0 + a_kq * 4);
        }
        #pragma unroll
        for (int ki = 0; ki < 8; ki++) {
            const int k = b_k + 4 * ki;
            cp16(bb + (uint32_t)((k * BSTR + b_nq * 4) * 4),
                 B + (long long)(k0 + k) * ldb + bn + b_nq * 4);
        }
        asm volatile("cp.async.commit_group;" ::: "memory");
    };

    const int nk = K / BK;
    fill(0, 0);
    int buf = 0;

    for (int ks = 0; ks < nk; ks++) {
        if (ks + 1 < nk) {
            fill(buf ^ 1, (ks + 1) * BK);
            asm volatile("cp.async.wait_group 1;" ::: "memory");
        } else {
            asm volatile("cp.async.wait_group 0;" ::: "memory");
        }
        __syncthreads();

        const uint32_t* Ab = (const uint32_t*)(As + buf * ASZ);
        const uint32_t* Bb = (const uint32_t*)(Bs + buf * BSZ);

        #pragma unroll
        for (int k8 = 0; k8 < 4; k8++) {
            const int kk = k8 * 8;
            uint32_t bf[8][2];
            #pragma unroll
            for (int nt = 0; nt < 8; nt++) {
                const int col = wn * 64 + nt * 8 + g;
                bf[nt][0] = Bb[(kk + t) * BSTR + col];
                bf[nt][1] = Bb[(kk + t + 4) * BSTR + col];
            }
            #pragma unroll
            for (int mt = 0; mt < 4; mt++) {
                const int row = wm * 64 + mt * 16 + g;
                uint32_t af[4];
                af[0] = Ab[row * ASTR + kk + t];
                af[1] = Ab[(row + 8) * ASTR + kk + t];
                af[2] = Ab[row * ASTR + kk + t + 4];
                af[3] = Ab[(row + 8) * ASTR + kk + t + 4];
                #pragma unroll
                for (int nt = 0; nt < 8; nt++)
                    mma8(acc[mt][nt], af, bf[nt]);
            }
        }
        __syncthreads();
        buf ^= 1;
    }

    // epilogue: c0:(g,2t) c1:(g,2t+1) c2:(g+8,2t) c3:(g+8,2t+1)
    #pragma unroll
    for (int mt = 0; mt < 4; mt++) {
        const int r0 = bm + wm * 64 + mt * 16 + g;
        const float bi0 = bias ? bias[r0]     : 0.f;
        const float bi1 = bias ? bias[r0 + 8] : 0.f;
        #pragma unroll
        for (int nt = 0; nt < 8; nt++) {
            const int c0 = bn + wn * 64 + nt * 8 + 2 * t;
            float2 v0, v1;
            v0.x = acc[mt][nt][0] * alpha + bi0;
            v0.y = acc[mt][nt][1] * alpha + bi0;
            v1.x = acc[mt][nt][2] * alpha + bi1;
            v1.y = acc[mt][nt][3] * alpha + bi1;
            if (R) {
                const float2 r0v = *(const float2*)&R[(long long)r0 * ldc + c0];
                const float2 r1v = *(const float2*)&R[(long long)(r0 + 8) * ldc + c0];
                v0.x += r0v.x; v0.y += r0v.y;
                v1.x += r1v.x; v1.y += r1v.y;
            }
            if (ROUND) {
                v0.x = f2tf32(v0.x); v0.y = f2tf32(v0.y);
                v1.x = f2tf32(v1.x); v1.y = f2tf32(v1.y);
            }
            *(float2*)&C[(long long)r0 * ldc + c0]       = v0;
            *(float2*)&C[(long long)(r0 + 8) * ldc + c0] = v1;
        }
    }
}

// ---------------- row softmax (writes tf32-rounded P) ------------------------
__global__ void __launch_bounds__(256)
softmax_kernel(float* __restrict__ sm)
{
    float* row = sm + (long long)blockIdx.x * LL;
    const int tid = threadIdx.x;
    const int warp = tid >> 5, lane = tid & 31;

    float v[8];
    float mx = -1e30f;
    #pragma unroll
    for (int i = 0; i < 8; i++) {
        v[i] = row[tid + 256 * i];
        mx = fmaxf(mx, v[i]);
    }
    __shared__ float red[32];
    __shared__ float bcast;
    #pragma unroll
    for (int o = 16; o; o >>= 1) mx = fmaxf(mx, __shfl_xor_sync(0xffffffffu, mx, o));
    if (!lane) red[warp] = mx;
    __syncthreads();
    if (tid < 32) {
        float m2 = (tid < 8) ? red[tid] : -1e30f;
        #pragma unroll
        for (int o = 4; o; o >>= 1) m2 = fmaxf(m2, __shfl_xor_sync(0xffffffffu, m2, o));
        if (!tid) bcast = m2;
    }
    __syncthreads();
    mx = bcast;

    float s = 0.f;
    #pragma unroll
    for (int i = 0; i < 8; i++) {
        v[i] = expf(v[i] - mx);
        s += v[i];
    }
    #pragma unroll
    for (int o = 16; o; o >>= 1) s += __shfl_xor_sync(0xffffffffu, s, o);
    if (!lane) red[warp] = s;
    __syncthreads();
    if (tid < 32) {
        float s2 = (tid < 8) ? red[tid] : 0.f;
        #pragma unroll
        for (int o = 4; o; o >>= 1) s2 += __shfl_xor_sync(0xffffffffu, s2, o);
        if (!tid) bcast = s2;
    }
    __syncthreads();
    const float inv = 1.f / bcast;
    #pragma unroll
    for (int i = 0; i < 8; i++) row[tid + 256 * i] = f2tf32(v[i] * inv);
}

// ---------------- launch ------------------------------------------------------
extern "C" void kernel_launch(void* const* d_in, const int* in_sizes, int n_in,
                              void* d_out, int out_size)
{
    const float* x  = (const float*)d_in[0];
    const float* gw = (const float*)d_in[1];
    const float* gb = (const float*)d_in[2];
    const float* wq = (const float*)d_in[3];
    const float* bq = (const float*)d_in[4];
    const float* wk = (const float*)d_in[5];
    const float* bk = (const float*)d_in[6];
    const float* wv = (const float*)d_in[7];
    const float* bv = (const float*)d_in[8];
    const float* wo = (const float*)d_in[9];
    const float* bo = (const float*)d_in[10];
    float* out = (float*)d_out;

    float *h, *ht, *q, *k, *v, *s, *w;
    cudaGetSymbolAddress((void**)&h,  g_h);
    cudaGetSymbolAddress((void**)&ht, g_ht);
    cudaGetSymbolAddress((void**)&q,  g_q);
    cudaGetSymbolAddress((void**)&k,  g_k);
    cudaGetSymbolAddress((void**)&v,  g_v);
    cudaGetSymbolAddress((void**)&s,  g_s);
    cudaGetSymbolAddress((void**)&w,  g_w);

    float* wqt = w;
    float* wkt = w + CC * CC;
    float* wvt = w + 2 * CC * CC;
    float* wot = w + 3 * CC * CC;

    cudaFuncSetAttribute(gemm_tf32_nn<true>,
                         cudaFuncAttributeMaxDynamicSharedMemorySize, GEMM_SMEM);
    cudaFuncSetAttribute(gemm_tf32_nn<false>,
                         cudaFuncAttributeMaxDynamicSharedMemorySize, GEMM_SMEM);

    const float scale = 0.044194173824159216f;   // 512^-0.5
    dim3 blk(256);

    // 0) tf32 copies of all weights
    cvt4_kernel<<<1024, 256>>>((const float4*)wq, (const float4*)wk,
                               (const float4*)wv, (const float4*)wo, (float4*)w);

    // 1) GroupNorm -> h [C][L] (tf32)
    gn_kernel<<<BB * NG, 256>>>(x, gw, gb, h);

    // 2) Q/K/V = W @ H_b + bias  (M=C, N=L, K=C; tf32-rounded outs)
    dim3 gQKV(LL / BN, CC / BM, BB);     // (8,4,8)
    gemm_tf32_nn<true><<<gQKV, blk, GEMM_SMEM>>>(
        wqt, 0LL, h, CL, bq, nullptr, 0LL, q, CL, CC, CC, LL, LL, 1.f);
    gemm_tf32_nn<true><<<gQKV, blk, GEMM_SMEM>>>(
        wkt, 0LL, h, CL, bk, nullptr, 0LL, k, CL, CC, CC, LL, LL, 1.f);
    gemm_tf32_nn<true><<<gQKV, blk, GEMM_SMEM>>>(
        wvt, 0LL, h, CL, bv, nullptr, 0LL, v, CL, CC, CC, LL, LL, 1.f);

    // 3) qT [L][C] into g_ht
    transpose_kernel<<<dim3(LL / 32, CC / 32, BB), 256>>>(q, ht, CC, LL);

    // 4) S = scale * qT @ k  (M=L, N=L, K=C; fp32 scores out)
    dim3 gS(LL / BN, LL / BM, BB);       // (8,16,8)
    gemm_tf32_nn<false><<<gS, blk, GEMM_SMEM>>>(
        ht, CL, k, CL, nullptr, nullptr, 0LL, s, LL2, CC, CC, LL, LL, scale);

    // 5) row softmax (tf32-rounded P)
    softmax_kernel<<<BB * LL, 256>>>(s);

    // 6) vT [L][C] into g_h (h dead after QKV)
    transpose_kernel<<<dim3(LL / 32, CC / 32, BB), 256>>>(v, h, CC, LL);

    // 7) h2T = P @ vT  (M=L, N=C, K=L; A=P has lda=LL!) into g_q (q dead)
    dim3 gA(CC / BN, LL / BM, BB);       // (2,16,8)
    gemm_tf32_nn<true><<<gA, blk, GEMM_SMEM>>>(
        s, LL2, h, CL, nullptr, nullptr, 0LL, q, CL, LL, LL, CC, CC, 1.f);

    // 8) h2 [C][L] into g_k (k dead after scores)
    transpose_kernel<<<dim3(CC / 32, LL / 32, BB), 256>>>(q, k, LL, CC);

    // 9) out = x + wo @ h2 + bo  (M=C, N=L, K=C; fp32 out)
    dim3 gO(LL / BN, CC / BM, BB);       // (8,4,8)
    gemm_tf32_nn<false><<<gO, blk, GEMM_SMEM>>>(
        wot, 0LL, k, CL, bo, x, CL, out, CL, CC, CC, LL, LL, 1.f);
}